// round 16
// baseline (speedup 1.0000x reference)
#include <cuda_runtime.h>
#include <cuda_bf16.h>
#include <math.h>
#include <stdint.h>

#define NB 8
#define DD 128
#define HW 1600
#define CC 1444
#define CAS 1728          // padded CA row stride
#define CAOFF 64
#define PAD 1664          // 13 * 128
#define MT 13
#define NSPLIT 3          // gemm2 k-split count (13x3x8 = 312 blocks ~ 1.05 waves)

typedef unsigned long long ull;
typedef __nv_bfloat16 bf16;

// -------- scratch (static device arrays, zero-initialized at load) --------
__device__ __align__(16) float d_bg[NB * HW * DD];                    //  6.6 MB
__device__ __align__(16) float d_M[(size_t)NB * HW * HW];             // 81.9 MB
__device__ __align__(16) float d_CApad[(size_t)NB * HW * CAS];        // 88.5 MB (borders stay 0)
__device__ __align__(16) bf16 d_ghi[NB * PAD * DD];
__device__ __align__(16) bf16 d_glo[NB * PAD * DD];
__device__ __align__(16) bf16 d_bghi[NB * PAD * DD];
__device__ __align__(16) bf16 d_bglo[NB * PAD * DD];
__device__ __align__(16) bf16 d_bgThi[NB * DD * PAD];
__device__ __align__(16) bf16 d_bgTlo[NB * DD * PAD];
__device__ __align__(16) bf16 d_Thi[(size_t)NB * PAD * PAD];          // 44.3 MB
__device__ __align__(16) bf16 d_Tlo[(size_t)NB * PAD * PAD];          // 44.3 MB
__device__ __align__(16) float d_Y8[(size_t)NSPLIT * NB * HW * DD];   // 19.7 MB
__device__ __align__(16) bf16 d_Wthi[DD * 256];                       // Wt hi [dout][k]
__device__ __align__(16) bf16 d_Wtlo[DD * 256];
__device__ float d_ng[NB * HW];
__device__ float d_k1d[NB * CC];
__device__ float d_wwd[NB * HW];
__device__ float d_zrowM[HW];        // stays zero
__device__ float d_zrowCA[CAS];      // stays zero
__device__ int d_tbase[CC];
__device__ int d_c2pad[CC];

__device__ __constant__ int OY9[9] = {-1,-1,-1, 0,0,0, 1,1,1};
__device__ __constant__ int OX9[9] = {-1, 0, 1,-1,0,1,-1,0,1};
__device__ __constant__ int OFFL9[9] = {-41,-40,-39,-1,0,1,39,40,41};

// ---------------- warp MMA + cp.async helpers ----------------
__device__ __forceinline__ uint32_t smem_u32(const void* p) {
    uint32_t a;
    asm("{ .reg .u64 t; cvta.to.shared.u64 t, %1; cvt.u32.u64 %0, t; }" : "=r"(a) : "l"(p));
    return a;
}

__device__ __forceinline__ void ldsm4(uint32_t& r0, uint32_t& r1, uint32_t& r2, uint32_t& r3,
                                      uint32_t addr) {
    asm volatile("ldmatrix.sync.aligned.m8n8.x4.shared.b16 {%0,%1,%2,%3}, [%4];"
                 : "=r"(r0), "=r"(r1), "=r"(r2), "=r"(r3) : "r"(addr));
}

__device__ __forceinline__ void mma16816(float* d, const uint32_t* a, uint32_t b0, uint32_t b1) {
    asm volatile("mma.sync.aligned.m16n8k16.row.col.f32.bf16.bf16.f32 "
                 "{%0,%1,%2,%3}, {%4,%5,%6,%7}, {%8,%9}, {%0,%1,%2,%3};"
                 : "+f"(d[0]), "+f"(d[1]), "+f"(d[2]), "+f"(d[3])
                 : "r"(a[0]), "r"(a[1]), "r"(a[2]), "r"(a[3]), "r"(b0), "r"(b1));
}

#define CPA16(sm, gp) asm volatile("cp.async.cg.shared.global [%0], [%1], 16;" :: "r"(sm), "l"(gp))
#define CPA_COMMIT()  asm volatile("cp.async.commit_group;" ::: "memory")
#define CPA_WAIT1()   asm volatile("cp.async.wait_group 1;" ::: "memory")
#define CPA_WAIT0()   asm volatile("cp.async.wait_group 0;" ::: "memory")

// smem tile: 128 rows x 40 bf16 (stride 40; 80B => conflict-free ldmatrix)
#define SSTR 40
#define BUFE (128 * SSTR)
#define BUFB (BUFE * 2)          // 10240 bytes
#define STAGE (4 * BUFB)         // Ah, Al, Bh, Bl = 40960 bytes
#define GSMEM (2 * STAGE)        // double buffered = 81920 bytes

union HU8 { bf16 h[8]; uint4 u; };

// stage one K-chunk (4 matrices of 128x32 bf16) into one smem stage via cp.async
__device__ __forceinline__ void stage_chunk(
    const bf16* pA, const bf16* pAl, int rsA,
    const bf16* pB, const bf16* pBl, int rsB,
    uint32_t sbase, int tid)
{
#pragma unroll
    for (int i = tid; i < 512; i += 256) {
        int r = i >> 2, c = (i & 3) * 8;
        uint32_t so = (uint32_t)((r * SSTR + c) * 2);
        CPA16(sbase + so,            pA  + (size_t)r * rsA + c);
        CPA16(sbase + BUFB + so,     pAl + (size_t)r * rsA + c);
        CPA16(sbase + 2 * BUFB + so, pB  + (size_t)r * rsB + c);
        CPA16(sbase + 3 * BUFB + so, pBl + (size_t)r * rsB + c);
    }
}

// shared inner compute: one 32-K chunk of the 128x128 tile from smem base
__device__ __forceinline__ void mma_chunk(uint32_t base, float (&acc)[2][8][4],
                                          int mbase, int nbase, int aro, int aco,
                                          int bro, int bco)
{
#pragma unroll
    for (int kk = 0; kk < 32; kk += 16) {
        uint32_t ah[2][4], al[2][4];
#pragma unroll
        for (int mi = 0; mi < 2; mi++) {
            uint32_t off = (uint32_t)(((mbase + mi * 16 + aro) * SSTR + kk + aco) * 2);
            ldsm4(ah[mi][0], ah[mi][1], ah[mi][2], ah[mi][3], base + off);
            ldsm4(al[mi][0], al[mi][1], al[mi][2], al[mi][3], base + BUFB + off);
        }
        uint32_t bh[4][4], bl[4][4];
#pragma unroll
        for (int ng = 0; ng < 4; ng++) {
            uint32_t off = (uint32_t)(((nbase + ng * 16 + bro) * SSTR + kk + bco) * 2);
            ldsm4(bh[ng][0], bh[ng][1], bh[ng][2], bh[ng][3], base + 2 * BUFB + off);
            ldsm4(bl[ng][0], bl[ng][1], bl[ng][2], bl[ng][3], base + 3 * BUFB + off);
        }
#pragma unroll
        for (int mi = 0; mi < 2; mi++)
#pragma unroll
            for (int nj = 0; nj < 8; nj++) {
                int ng = nj >> 1;
                uint32_t b0h = (nj & 1) ? bh[ng][2] : bh[ng][0];
                uint32_t b1h = (nj & 1) ? bh[ng][3] : bh[ng][1];
                uint32_t b0l = (nj & 1) ? bl[ng][2] : bl[ng][0];
                uint32_t b1l = (nj & 1) ? bl[ng][3] : bl[ng][1];
                mma16816(acc[mi][nj], ah[mi], b0h, b1h);
                mma16816(acc[mi][nj], ah[mi], b0l, b1l);
                mma16816(acc[mi][nj], al[mi], b0h, b1h);
            }
    }
}

// double-buffered core mainloop
__device__ __forceinline__ void gemm_core_db(
    const bf16* __restrict__ Ah, const bf16* __restrict__ Al, int rsA,
    const bf16* __restrict__ Bh, const bf16* __restrict__ Bl, int rsB,
    int nChunks, float (&acc)[2][8][4], char* smem, int tid)
{
    uint32_t sb = smem_u32(smem);
    int wid = tid >> 5, lane = tid & 31;
    int mbase = (wid & 3) * 32, nbase = (wid >> 2) * 64;
    int aro = (lane & 7) + ((lane >> 3) & 1) * 8;
    int aco = (lane >> 4) * 8;
    int bro = (lane & 7) + ((lane >> 4) & 1) * 8;
    int bco = ((lane >> 3) & 1) * 8;

    stage_chunk(Ah, Al, rsA, Bh, Bl, rsB, sb, tid);
    CPA_COMMIT();

    for (int ch = 0; ch < nChunks; ch++) {
        int cur = ch & 1;
        if (ch + 1 < nChunks) {
            stage_chunk(Ah + (ch + 1) * 32, Al + (ch + 1) * 32, rsA,
                        Bh + (ch + 1) * 32, Bl + (ch + 1) * 32, rsB,
                        sb + (cur ^ 1) * STAGE, tid);
            CPA_COMMIT();
            CPA_WAIT1();
        } else {
            CPA_WAIT0();
        }
        __syncthreads();
        mma_chunk(sb + cur * STAGE, acc, mbase, nbase, aro, aco, bro, bco);
        __syncthreads();
    }
}

// ---------------- k_tab: index lookup tables ----------------
__global__ void k_tab() {
    int i = blockIdx.x * 256 + threadIdx.x;
    if (i < CC) {
        int qy = i / 38 + 1, qx = i % 38 + 1;
        d_tbase[i] = qy * 40 + qx;
        d_c2pad[i] = CAOFF + qy * 40 + qx;
    }
}

// ---------------- k_prepW: Wt = W^T split hi/lo ----------------
__global__ void k_prepW(const float* __restrict__ W) {
    int i = blockIdx.x * 256 + threadIdx.x;   // 32768
    int dout = i >> 8, k = i & 255;
    float w = W[k * DD + dout];
    bf16 h = __float2bfloat16(w);
    d_Wthi[i] = h;
    d_Wtlo[i] = __float2bfloat16(w - __bfloat162float(h));
}

// ---------------- prep1: bg, bf16 splits, per-pixel |g|^2 ----------------
__global__ __launch_bounds__(128) void k_prep1(const float* __restrict__ g,
                                               const float* __restrict__ mask) {
    int p = blockIdx.x;
    int b = p / HW, r = p - b * HW;
    int d = threadIdx.x;
    size_t gi = (size_t)p * DD + d;
    float gv = g[gi];
    float m = mask[p];
    float bgv = gv * m;
    d_bg[gi] = bgv;
    size_t pi = ((size_t)b * PAD + r) * DD + d;
    bf16 gh = __float2bfloat16(gv);
    bf16 gl = __float2bfloat16(gv - __bfloat162float(gh));
    bf16 bh = __float2bfloat16(bgv);
    bf16 bl = __float2bfloat16(bgv - __bfloat162float(bh));
    d_ghi[pi] = gh; d_glo[pi] = gl;
    d_bghi[pi] = bh; d_bglo[pi] = bl;
    float s = gv * gv;
#pragma unroll
    for (int o = 16; o; o >>= 1) s += __shfl_xor_sync(0xffffffffu, s, o);
    __shared__ float red[4];
    if ((d & 31) == 0) red[d >> 5] = s;
    __syncthreads();
    if (d == 0) d_ng[p] = red[0] + red[1] + red[2] + red[3];
}

// ---------------- prep2 (no smem staging): k1d, wwd directly from L2 ----------------
__global__ __launch_bounds__(256) void k_prep2(const float* __restrict__ mask) {
    int b = blockIdx.y;
    int i = blockIdx.x * 256 + threadIdx.x;   // 0..1791
    const float* ng = d_ng + b * HW;
    const float* ms = mask + b * HW;
    if (i < CC) {
        int r = i / 38, j = i - r * 38;
        float s = 0.f;
#pragma unroll
        for (int dy = 0; dy < 3; dy++)
#pragma unroll
            for (int dx = 0; dx < 3; dx++) {
                int q = (r + dy) * 40 + (j + dx);
                s += ng[q] * ms[q];
            }
        d_k1d[b * CC + i] = s;
    }
    if (i < HW) {
        int y = i / 40, x = i - y * 40;
        float s = 0.f;
#pragma unroll
        for (int oy = -1; oy <= 1; oy++)
#pragma unroll
            for (int ox = -1; ox <= 1; ox++) {
                int yy = y + oy, xx = x + ox;
                if (yy >= 0 && yy < 40 && xx >= 0 && xx < 40) s += ng[yy * 40 + xx];
            }
        d_wwd[b * HW + i] = s;
    }
}

// ---------------- prepT: bgT[d][q] = bg[q][d] (bf16 hi/lo, padded q) ----------------
__global__ __launch_bounds__(256) void k_prepT() {
    int b = blockIdx.y;
    int q0 = blockIdx.x * 64;
    __shared__ bf16 shi[64][DD + 2], slo[64][DD + 2];
    int tid = threadIdx.x;
    for (int i = tid; i < 64 * DD; i += 256) {
        int qq = i >> 7, dc = i & 127;
        int q = q0 + qq;
        bf16 h = __float2bfloat16(0.f), l = h;
        if (q < HW) {
            size_t src = ((size_t)b * PAD + q) * DD + dc;
            h = d_bghi[src]; l = d_bglo[src];
        }
        shi[qq][dc] = h; slo[qq][dc] = l;
    }
    __syncthreads();
    for (int i = tid; i < DD * 64; i += 256) {
        int dr = i >> 6, qq = i & 63;
        size_t dst = ((size_t)b * DD + dr) * PAD + q0 + qq;
        d_bgThi[dst] = shi[qq][dr];
        d_bgTlo[dst] = slo[qq][dr];
    }
}

// ---------------- GEMM1 (mma.sync, cp.async db): M = g @ bg^T ----------------
__global__ __launch_bounds__(256) void k_gemm1_mma() {
    extern __shared__ char smem[];
    int b = blockIdx.z, nt = blockIdx.x, mt = blockIdx.y;
    int tid = threadIdx.x;
    float acc[2][8][4];
#pragma unroll
    for (int i = 0; i < 2; i++)
#pragma unroll
        for (int j = 0; j < 8; j++)
#pragma unroll
            for (int k = 0; k < 4; k++) acc[i][j][k] = 0.f;

    const bf16* Ah = d_ghi + ((size_t)b * PAD + mt * 128) * DD;
    const bf16* Al = d_glo + ((size_t)b * PAD + mt * 128) * DD;
    const bf16* Bh = d_bghi + ((size_t)b * PAD + nt * 128) * DD;
    const bf16* Bl = d_bglo + ((size_t)b * PAD + nt * 128) * DD;
    gemm_core_db(Ah, Al, DD, Bh, Bl, DD, 4, acc, smem, tid);

    int wid = tid >> 5, lane = tid & 31;
    int mw = (wid & 3) * 32, nw = (wid >> 2) * 64;
    float* Mo = d_M + (size_t)b * HW * HW;
#pragma unroll
    for (int mi = 0; mi < 2; mi++)
#pragma unroll
        for (int nj = 0; nj < 8; nj++) {
            int m0 = mt * 128 + mw + mi * 16 + (lane >> 2);
            int n = nt * 128 + nw + nj * 8 + (lane & 3) * 2;
            if (n < HW) {
                if (m0 < HW) *(float2*)&Mo[(size_t)m0 * HW + n] = make_float2(acc[mi][nj][0], acc[mi][nj][1]);
                if (m0 + 8 < HW) *(float2*)&Mo[(size_t)(m0 + 8) * HW + n] = make_float2(acc[mi][nj][2], acc[mi][nj][3]);
            }
        }
}

// ---------------- block reductions, 512 threads ----------------
__device__ __forceinline__ float2 bsum2_512(float a, float b, volatile float* red) {
#pragma unroll
    for (int o = 16; o; o >>= 1) {
        a += __shfl_xor_sync(0xffffffffu, a, o);
        b += __shfl_xor_sync(0xffffffffu, b, o);
    }
    int lane = threadIdx.x & 31;
    int w = threadIdx.x >> 5;
    if (lane == 0) { red[w] = a; red[16 + w] = b; }
    __syncthreads();
    if (threadIdx.x < 32) {
        a = (lane < 16) ? red[lane] : 0.f;
        b = (lane < 16) ? red[16 + lane] : 0.f;
#pragma unroll
        for (int o = 8; o; o >>= 1) {
            a += __shfl_xor_sync(0xffffffffu, a, o);
            b += __shfl_xor_sync(0xffffffffu, b, o);
        }
        if (lane == 0) { red[0] = a; red[16] = b; }
    }
    __syncthreads();
    float2 r = make_float2(red[0], red[16]);
    __syncthreads();
    return r;
}

__device__ __forceinline__ float4 bsum4_512(float a, float b, float c, float d,
                                            volatile float* red) {
#pragma unroll
    for (int o = 16; o; o >>= 1) {
        a += __shfl_xor_sync(0xffffffffu, a, o);
        b += __shfl_xor_sync(0xffffffffu, b, o);
        c += __shfl_xor_sync(0xffffffffu, c, o);
        d += __shfl_xor_sync(0xffffffffu, d, o);
    }
    int lane = threadIdx.x & 31;
    int w = threadIdx.x >> 5;
    if (lane == 0) { red[w] = a; red[16 + w] = b; red[32 + w] = c; red[48 + w] = d; }
    __syncthreads();
    if (threadIdx.x < 32) {
        a = (lane < 16) ? red[lane] : 0.f;
        b = (lane < 16) ? red[16 + lane] : 0.f;
        c = (lane < 16) ? red[32 + lane] : 0.f;
        d = (lane < 16) ? red[48 + lane] : 0.f;
#pragma unroll
        for (int o = 8; o; o >>= 1) {
            a += __shfl_xor_sync(0xffffffffu, a, o);
            b += __shfl_xor_sync(0xffffffffu, b, o);
            c += __shfl_xor_sync(0xffffffffu, c, o);
            d += __shfl_xor_sync(0xffffffffu, d, o);
        }
        if (lane == 0) { red[0] = a; red[16] = b; red[32] = c; red[48] = d; }
    }
    __syncthreads();
    float4 r = make_float4(red[0], red[16], red[32], red[48]);
    __syncthreads();
    return r;
}

// ---------------- k3 (paired locs): softmax for loc0 and loc0+1 per block ----------------
__global__ __launch_bounds__(512) void k3_softmax() {
    int bx = blockIdx.x;            // NB * 800
    int b = bx / 800;
    int pi = bx - b * 800;
    int py = pi / 20, pxp = (pi - py * 20) * 2;
    int loc0 = py * 40 + pxp;
    int tid = threadIdx.x;
    __shared__ float red[64];

    const float* Mb = d_M + (size_t)b * HW * HW;
    float wwd0 = d_wwd[b * HW + loc0];
    float wwd1 = d_wwd[b * HW + loc0 + 1];
    const float* k1 = d_k1d + b * CC;
    bool interior = (py >= 1 && py <= 38 && pxp >= 1 && pxp <= 37);

    float dsr0[3], dsr1[3];
    float s0 = 0.f, s20 = 0.f, s1 = 0.f, s21 = 0.f;
    if (interior) {
        const float* P = Mb + (size_t)loc0 * HW;
#pragma unroll
        for (int e = 0; e < 3; e++) {
            int c = tid + 512 * e;
            int cc = c < CC ? c : CC - 1;
            int base = d_tbase[cc];
            float cs0 = 0.f, cs1 = 0.f;
#pragma unroll
            for (int k = 0; k < 9; k++) {
                cs0 += P[base + OFFL9[k] * (HW + 1)];
                cs1 += P[base + OFFL9[k] * (HW + 1) + HW];
            }
            float dv0 = k1[cc] + wwd0 - 2.f * cs0;
            float dv1 = k1[cc] + wwd1 - 2.f * cs1;
            dsr0[e] = dv0; dsr1[e] = dv1;
            if (c < CC) { s0 += dv0; s20 += dv0 * dv0; s1 += dv1; s21 += dv1 * dv1; }
        }
    } else {
        for (int li = 0; li < 2; li++) {
            int px = pxp + li;
            const float* rowsO[9];
#pragma unroll
            for (int k = 0; k < 9; k++) {
                int y = py + OY9[k], x = px + OX9[k];
                bool v = (y >= 0 && y < 40 && x >= 0 && x < 40);
                rowsO[k] = (v ? (Mb + (size_t)(y * 40 + x) * HW) : d_zrowM) + OFFL9[k];
            }
            float wwd = li ? wwd1 : wwd0;
#pragma unroll
            for (int e = 0; e < 3; e++) {
                int c = tid + 512 * e;
                int cc = c < CC ? c : CC - 1;
                int base = d_tbase[cc];
                float cs = 0.f;
#pragma unroll
                for (int k = 0; k < 9; k++) cs += rowsO[k][base];
                float dv = k1[cc] + wwd - 2.f * cs;
                if (li == 0) dsr0[e] = dv; else dsr1[e] = dv;
                if (c < CC) {
                    if (li == 0) { s0 += dv; s20 += dv * dv; }
                    else { s1 += dv; s21 += dv * dv; }
                }
            }
        }
    }
    float4 mv = bsum4_512(s0, s20, s1, s21, red);
    float mu0 = mv.x * (1.f / CC), ex20 = mv.y * (1.f / CC);
    float mu1 = mv.z * (1.f / CC), ex21 = mv.w * (1.f / CC);
    float inv0 = rsqrtf(fmaxf(ex20 - mu0 * mu0, 0.f));
    float inv1 = rsqrtf(fmaxf(ex21 - mu1 * mu1, 0.f));

    float evr0[3], evr1[3];
    float es0 = 0.f, es1 = 0.f;
#pragma unroll
    for (int e = 0; e < 3; e++) {
        int c = tid + 512 * e;
        {
            float z = (dsr0[e] - mu0) * inv0;
            float a = fabsf(z);
            float ex = __expf(-2.f * a);
            float r = __fdividef(100.f, 1.f + ex);
            float val = (z >= 0.f) ? r : 100.f - r;
            float ev = __expf(-val);
            evr0[e] = ev;
            if (c < CC) es0 += ev;
        }
        {
            float z = (dsr1[e] - mu1) * inv1;
            float a = fabsf(z);
            float ex = __expf(-2.f * a);
            float r = __fdividef(100.f, 1.f + ex);
            float val = (z >= 0.f) ? r : 100.f - r;
            float ev = __expf(-val);
            evr1[e] = ev;
            if (c < CC) es1 += ev;
        }
    }
    float2 est = bsum2_512(es0, es1, red);
    float it0 = 1.f / est.x, it1 = 1.f / est.y;

    float* car0 = d_CApad + (size_t)(b * HW + loc0) * CAS;
    float* car1 = car0 + CAS;
#pragma unroll
    for (int e = 0; e < 3; e++) {
        int c = tid + 512 * e;
        if (c < CC) {
            int idx = d_c2pad[c];
            car0[idx] = evr0[e] * it0;
            car1[idx] = evr1[e] * it1;
        }
    }
}

// ---------------- k4 (paired p's, 512 thr): T rows p0, p0+1 (bf16 hi/lo, padded) ----------------
__global__ __launch_bounds__(512) void k4_buildT() {
    int bx = blockIdx.x;            // NB * 800
    int b = bx / 800;
    int pi = bx - b * 800;
    int py = pi / 20, pxp = (pi - py * 20) * 2;
    int p0 = py * 40 + pxp;
    const float* cab = d_CApad + (size_t)b * HW * CAS;
    bool interior = (py >= 1 && py <= 38 && pxp >= 1 && pxp <= 37);
    size_t tb0 = ((size_t)b * PAD + p0) * PAD;
    size_t tb1 = tb0 + PAD;

    if (interior) {
        const float* Q = cab + (size_t)p0 * CAS + CAOFF;
        for (int q = threadIdx.x; q < HW; q += 512) {
            float t0 = 0.f, t1 = 0.f;
#pragma unroll
            for (int k = 0; k < 9; k++) {
                t0 += Q[q - OFFL9[k] * (CAS + 1)];
                t1 += Q[q - OFFL9[k] * (CAS + 1) + CAS];
            }
            bf16 h0 = __float2bfloat16(t0);
            d_Thi[tb0 + q] = h0;
            d_Tlo[tb0 + q] = __float2bfloat16(t0 - __bfloat162float(h0));
            bf16 h1 = __float2bfloat16(t1);
            d_Thi[tb1 + q] = h1;
            d_Tlo[tb1 + q] = __float2bfloat16(t1 - __bfloat162float(h1));
        }
    } else {
        for (int li = 0; li < 2; li++) {
            int px = pxp + li;
            size_t tb = li ? tb1 : tb0;
            const float* rowsO[9];
#pragma unroll
            for (int k = 0; k < 9; k++) {
                int ly = py - OY9[k], lx = px - OX9[k];
                bool v = (ly >= 0 && ly < 40 && lx >= 0 && lx < 40);
                rowsO[k] = (v ? (cab + (size_t)(ly * 40 + lx) * CAS) : d_zrowCA) + (CAOFF - OFFL9[k]);
            }
            for (int q = threadIdx.x; q < HW; q += 512) {
                float tsum = 0.f;
#pragma unroll
                for (int k = 0; k < 9; k++) tsum += rowsO[k][q];
                bf16 h = __float2bfloat16(tsum);
                d_Thi[tb + q] = h;
                d_Tlo[tb + q] = __float2bfloat16(tsum - __bfloat162float(h));
            }
        }
    }
    if (threadIdx.x < PAD - HW) {
        bf16 z = __float2bfloat16(0.f);
        d_Thi[tb0 + HW + threadIdx.x] = z;
        d_Tlo[tb0 + HW + threadIdx.x] = z;
        d_Thi[tb1 + HW + threadIdx.x] = z;
        d_Tlo[tb1 + HW + threadIdx.x] = z;
    }
}

// ---------------- GEMM2 (mma.sync, cp.async db): Y = T @ bg, 3-way K-split ----------------
// chunks of 32 along K (q): 50 chunks total; split s gets {17,17,16}
__global__ __launch_bounds__(256) void k_gemm2_mma() {
    extern __shared__ char smem[];
    int b = blockIdx.z, mt = blockIdx.x, s = blockIdx.y;
    int tid = threadIdx.x;
    int kc0 = (s < 2) ? 17 * s : 34;
    int nch = (s < 2) ? 17 : 16;

    float acc[2][8][4];
#pragma unroll
    for (int i = 0; i < 2; i++)
#pragma unroll
        for (int j = 0; j < 8; j++)
#pragma unroll
            for (int k = 0; k < 4; k++) acc[i][j][k] = 0.f;

    const bf16* Ah = d_Thi + ((size_t)b * PAD + mt * 128) * PAD + kc0 * 32;
    const bf16* Al = d_Tlo + ((size_t)b * PAD + mt * 128) * PAD + kc0 * 32;
    const bf16* Bh = d_bgThi + (size_t)b * DD * PAD + kc0 * 32;
    const bf16* Bl = d_bgTlo + (size_t)b * DD * PAD + kc0 * 32;
    gemm_core_db(Ah, Al, PAD, Bh, Bl, PAD, nch, acc, smem, tid);

    int wid = tid >> 5, lane = tid & 31;
    int mw = (wid & 3) * 32, nw = (wid >> 2) * 64;
    float* Yo = d_Y8 + ((size_t)s * NB + b) * HW * DD;
#pragma unroll
    for (int mi = 0; mi < 2; mi++)
#pragma unroll
        for (int nj = 0; nj < 8; nj++) {
            int m0 = mt * 128 + mw + mi * 16 + (lane >> 2);
            int n = nw + nj * 8 + (lane & 3) * 2;
            if (m0 < HW) *(float2*)&Yo[(size_t)m0 * DD + n] = make_float2(acc[mi][nj][0], acc[mi][nj][1]);
            if (m0 + 8 < HW) *(float2*)&Yo[(size_t)(m0 + 8) * DD + n] = make_float2(acc[mi][nj][2], acc[mi][nj][3]);
        }
}

// ---------------- k5 (mma): out = ELU(con @ W + bias), con built on the fly ----------------
__global__ __launch_bounds__(256) void k5_mma(const float* __restrict__ mask,
                                              const float* __restrict__ bias,
                                              float* __restrict__ out) {
    __shared__ bf16 smem5[4 * BUFE];   // 40 KB: Ah, Al, Bh, Bl
    int mt = blockIdx.x, b = blockIdx.y;
    int tid = threadIdx.x;
    int P0 = mt * 128;
    uint32_t sb = smem_u32(smem5);
    const size_t YSTR = (size_t)NB * HW * DD;

    int wid = tid >> 5, lane = tid & 31;
    int mbase = (wid & 3) * 32, nbase = (wid >> 2) * 64;
    int aro = (lane & 7) + ((lane >> 3) & 1) * 8;
    int aco = (lane >> 4) * 8;
    int bro = (lane & 7) + ((lane >> 4) & 1) * 8;
    int bco = ((lane >> 3) & 1) * 8;

    int ar = tid >> 1, ac0 = (tid & 1) * 16;
    int pa = P0 + ar;
    int pc = pa < HW ? pa : HW - 1;
    float mval = mask[b * HW + pc];
    float w1m = (1.f - mval) * (1.f / 9.f);
    size_t gbase = ((size_t)b * HW + pc) * DD;

    float acc[2][8][4];
#pragma unroll
    for (int i = 0; i < 2; i++)
#pragma unroll
        for (int j = 0; j < 8; j++)
#pragma unroll
            for (int k = 0; k < 4; k++) acc[i][j][k] = 0.f;

    for (int ch = 0; ch < 8; ch++) {
        int k0 = ch * 32;
        __syncthreads();
#pragma unroll
        for (int i = tid; i < 512; i += 256) {
            int r = i >> 2, c = (i & 3) * 8;
            uint32_t so = (uint32_t)((r * SSTR + c) * 2);
            CPA16(sb + 2 * BUFB + so, d_Wthi + r * 256 + k0 + c);
            CPA16(sb + 3 * BUFB + so, d_Wtlo + r * 256 + k0 + c);
        }
        if (ch < 4) {
#pragma unroll
            for (int i = tid; i < 512; i += 256) {
                int r = i >> 2, c = (i & 3) * 8;
                uint32_t so = (uint32_t)((r * SSTR + c) * 2);
                CPA16(sb + so,        d_ghi + ((size_t)b * PAD + P0 + r) * DD + k0 + c);
                CPA16(sb + BUFB + so, d_glo + ((size_t)b * PAD + P0 + r) * DD + k0 + c);
            }
        } else {
            int d0 = (k0 - 128) + ac0;
            size_t gi = gbase + d0;
            float v[16];
#pragma unroll
            for (int j = 0; j < 16; j += 4) {
                float4 bgv = *(const float4*)&d_bg[gi + j];
                float4 y0 = *(const float4*)&d_Y8[0 * YSTR + gi + j];
                float4 y1 = *(const float4*)&d_Y8[1 * YSTR + gi + j];
                float4 y2 = *(const float4*)&d_Y8[2 * YSTR + gi + j];
                v[j + 0] = bgv.x + (y0.x + y1.x + y2.x) * w1m;
                v[j + 1] = bgv.y + (y0.y + y1.y + y2.y) * w1m;
                v[j + 2] = bgv.z + (y0.z + y1.z + y2.z) * w1m;
                v[j + 3] = bgv.w + (y0.w + y1.w + y2.w) * w1m;
            }
            HU8 hh, ll;
#pragma unroll
            for (int g2 = 0; g2 < 2; g2++) {
#pragma unroll
                for (int j = 0; j < 8; j++) {
                    float fv = v[g2 * 8 + j];
                    bf16 h = __float2bfloat16(fv);
                    hh.h[j] = h;
                    ll.h[j] = __float2bfloat16(fv - __bfloat162float(h));
                }
                *(uint4*)((char*)smem5 + (ar * SSTR + ac0 + g2 * 8) * 2) = hh.u;
                *(uint4*)((char*)smem5 + BUFB + (ar * SSTR + ac0 + g2 * 8) * 2) = ll.u;
            }
        }
        CPA_COMMIT();
        CPA_WAIT0();
        __syncthreads();
        mma_chunk(sb, acc, mbase, nbase, aro, aco, bro, bco);
    }

    int mw = (wid & 3) * 32, nw = (wid >> 2) * 64;
#pragma unroll
    for (int mi = 0; mi < 2; mi++)
#pragma unroll
        for (int nj = 0; nj < 8; nj++) {
            int m0 = P0 + mw + mi * 16 + (lane >> 2);
            int n = nw + nj * 8 + (lane & 3) * 2;
            float b0 = bias[n], b1 = bias[n + 1];
            float v0 = acc[mi][nj][0] + b0, v1 = acc[mi][nj][1] + b1;
            float v2 = acc[mi][nj][2] + b0, v3 = acc[mi][nj][3] + b1;
            v0 = v0 > 0.f ? v0 : expm1f(v0);
            v1 = v1 > 0.f ? v1 : expm1f(v1);
            v2 = v2 > 0.f ? v2 : expm1f(v2);
            v3 = v3 > 0.f ? v3 : expm1f(v3);
            if (m0 < HW) *(float2*)&out[((size_t)b * HW + m0) * DD + n] = make_float2(v0, v1);
            if (m0 + 8 < HW) *(float2*)&out[((size_t)b * HW + m0 + 8) * DD + n] = make_float2(v2, v3);
        }
}

// ---------------- launch ----------------
extern "C" void kernel_launch(void* const* d_in, const int* in_sizes, int n_in,
                              void* d_out, int out_size) {
    const float* g    = (const float*)d_in[0];
    const float* mask = (const float*)d_in[1];
    const float* Wm   = (const float*)d_in[2];
    const float* bias = (const float*)d_in[3];
    float* out = (float*)d_out;

    cudaFuncSetAttribute(k_gemm1_mma, cudaFuncAttributeMaxDynamicSharedMemorySize, GSMEM);
    cudaFuncSetAttribute(k_gemm2_mma, cudaFuncAttributeMaxDynamicSharedMemorySize, GSMEM);

    k_tab<<<6, 256>>>();
    k_prepW<<<128, 256>>>(Wm);
    k_prep1<<<NB * HW, 128>>>(g, mask);
    k_prep2<<<dim3(7, NB), 256>>>(mask);
    k_prepT<<<dim3(PAD / 64, NB), 256>>>();
    k_gemm1_mma<<<dim3(MT, MT, NB), 256, GSMEM>>>();
    k3_softmax<<<NB * 800, 512>>>();
    k4_buildT<<<NB * 800, 512>>>();
    k_gemm2_mma<<<dim3(MT, NSPLIT, NB), 256, GSMEM>>>();
    k5_mma<<<dim3(MT, NB), 256>>>(mask, bias, out);
}

// round 17
// speedup vs baseline: 1.0488x; 1.0488x over previous
#include <cuda_runtime.h>
#include <cuda_bf16.h>
#include <math.h>
#include <stdint.h>

#define NB 8
#define DD 128
#define HW 1600
#define CC 1444
#define CAS 1728          // padded CA row stride
#define CAOFF 64
#define PAD 1664          // 13 * 128
#define MT 13
#define NSPLIT 4          // gemm2 k-split count

typedef unsigned long long ull;
typedef __nv_bfloat16 bf16;

// -------- scratch (static device arrays, zero-initialized at load) --------
__device__ __align__(16) float d_bg[NB * HW * DD];                    //  6.6 MB
__device__ __align__(16) float d_M[(size_t)NB * HW * HW];             // 81.9 MB
__device__ __align__(16) float d_CApad[(size_t)NB * HW * CAS];        // 88.5 MB (borders stay 0)
__device__ __align__(16) bf16 d_ghi[NB * PAD * DD];
__device__ __align__(16) bf16 d_glo[NB * PAD * DD];
__device__ __align__(16) bf16 d_bghi[NB * PAD * DD];
__device__ __align__(16) bf16 d_bglo[NB * PAD * DD];
__device__ __align__(16) bf16 d_bgThi[NB * DD * PAD];
__device__ __align__(16) bf16 d_bgTlo[NB * DD * PAD];
__device__ __align__(16) bf16 d_Thi[(size_t)NB * PAD * PAD];          // 44.3 MB
__device__ __align__(16) bf16 d_Tlo[(size_t)NB * PAD * PAD];          // 44.3 MB
__device__ __align__(16) float d_Y8[(size_t)NSPLIT * NB * HW * DD];   // 26.2 MB
__device__ __align__(16) bf16 d_Wthi[DD * 256];                       // Wt hi [dout][k]
__device__ __align__(16) bf16 d_Wtlo[DD * 256];
__device__ float d_ng[NB * HW];
__device__ float d_k1d[NB * CC];
__device__ float d_wwd[NB * HW];
__device__ float d_zrowM[HW];        // stays zero
__device__ float d_zrowCA[CAS];      // stays zero
__device__ int d_tbase[CC];
__device__ int d_c2pad[CC];

__device__ __constant__ int OY9[9] = {-1,-1,-1, 0,0,0, 1,1,1};
__device__ __constant__ int OX9[9] = {-1, 0, 1,-1,0,1,-1,0,1};
__device__ __constant__ int OFFL9[9] = {-41,-40,-39,-1,0,1,39,40,41};

// ---------------- warp MMA + cp.async helpers ----------------
__device__ __forceinline__ uint32_t smem_u32(const void* p) {
    uint32_t a;
    asm("{ .reg .u64 t; cvta.to.shared.u64 t, %1; cvt.u32.u64 %0, t; }" : "=r"(a) : "l"(p));
    return a;
}

__device__ __forceinline__ void ldsm4(uint32_t& r0, uint32_t& r1, uint32_t& r2, uint32_t& r3,
                                      uint32_t addr) {
    asm volatile("ldmatrix.sync.aligned.m8n8.x4.shared.b16 {%0,%1,%2,%3}, [%4];"
                 : "=r"(r0), "=r"(r1), "=r"(r2), "=r"(r3) : "r"(addr));
}

__device__ __forceinline__ void mma16816(float* d, const uint32_t* a, uint32_t b0, uint32_t b1) {
    asm volatile("mma.sync.aligned.m16n8k16.row.col.f32.bf16.bf16.f32 "
                 "{%0,%1,%2,%3}, {%4,%5,%6,%7}, {%8,%9}, {%0,%1,%2,%3};"
                 : "+f"(d[0]), "+f"(d[1]), "+f"(d[2]), "+f"(d[3])
                 : "r"(a[0]), "r"(a[1]), "r"(a[2]), "r"(a[3]), "r"(b0), "r"(b1));
}

#define CPA16(sm, gp) asm volatile("cp.async.cg.shared.global [%0], [%1], 16;" :: "r"(sm), "l"(gp))
#define CPA_COMMIT()  asm volatile("cp.async.commit_group;" ::: "memory")
#define CPA_WAIT1()   asm volatile("cp.async.wait_group 1;" ::: "memory")
#define CPA_WAIT0()   asm volatile("cp.async.wait_group 0;" ::: "memory")

// smem tile: 128 rows x 40 bf16 (stride 40; 80B => conflict-free ldmatrix)
#define SSTR 40
#define BUFE (128 * SSTR)
#define BUFB (BUFE * 2)          // 10240 bytes
#define STAGE (4 * BUFB)         // Ah, Al, Bh, Bl = 40960 bytes
#define GSMEM (2 * STAGE)        // double buffered = 81920 bytes

union HU8 { bf16 h[8]; uint4 u; };

// stage one K-chunk (4 matrices of 128x32 bf16) into one smem stage via cp.async
__device__ __forceinline__ void stage_chunk(
    const bf16* pA, const bf16* pAl, int rsA,
    const bf16* pB, const bf16* pBl, int rsB,
    uint32_t sbase, int tid)
{
#pragma unroll
    for (int i = tid; i < 512; i += 256) {
        int r = i >> 2, c = (i & 3) * 8;
        uint32_t so = (uint32_t)((r * SSTR + c) * 2);
        CPA16(sbase + so,            pA  + (size_t)r * rsA + c);
        CPA16(sbase + BUFB + so,     pAl + (size_t)r * rsA + c);
        CPA16(sbase + 2 * BUFB + so, pB  + (size_t)r * rsB + c);
        CPA16(sbase + 3 * BUFB + so, pBl + (size_t)r * rsB + c);
    }
}

// shared inner compute: one 32-K chunk of the 128x128 tile from smem base
__device__ __forceinline__ void mma_chunk(uint32_t base, float (&acc)[2][8][4],
                                          int mbase, int nbase, int aro, int aco,
                                          int bro, int bco)
{
#pragma unroll
    for (int kk = 0; kk < 32; kk += 16) {
        uint32_t ah[2][4], al[2][4];
#pragma unroll
        for (int mi = 0; mi < 2; mi++) {
            uint32_t off = (uint32_t)(((mbase + mi * 16 + aro) * SSTR + kk + aco) * 2);
            ldsm4(ah[mi][0], ah[mi][1], ah[mi][2], ah[mi][3], base + off);
            ldsm4(al[mi][0], al[mi][1], al[mi][2], al[mi][3], base + BUFB + off);
        }
        uint32_t bh[4][4], bl[4][4];
#pragma unroll
        for (int ng = 0; ng < 4; ng++) {
            uint32_t off = (uint32_t)(((nbase + ng * 16 + bro) * SSTR + kk + bco) * 2);
            ldsm4(bh[ng][0], bh[ng][1], bh[ng][2], bh[ng][3], base + 2 * BUFB + off);
            ldsm4(bl[ng][0], bl[ng][1], bl[ng][2], bl[ng][3], base + 3 * BUFB + off);
        }
#pragma unroll
        for (int mi = 0; mi < 2; mi++)
#pragma unroll
            for (int nj = 0; nj < 8; nj++) {
                int ng = nj >> 1;
                uint32_t b0h = (nj & 1) ? bh[ng][2] : bh[ng][0];
                uint32_t b1h = (nj & 1) ? bh[ng][3] : bh[ng][1];
                uint32_t b0l = (nj & 1) ? bl[ng][2] : bl[ng][0];
                uint32_t b1l = (nj & 1) ? bl[ng][3] : bl[ng][1];
                mma16816(acc[mi][nj], ah[mi], b0h, b1h);
                mma16816(acc[mi][nj], ah[mi], b0l, b1l);
                mma16816(acc[mi][nj], al[mi], b0h, b1h);
            }
    }
}

// double-buffered core mainloop
__device__ __forceinline__ void gemm_core_db(
    const bf16* __restrict__ Ah, const bf16* __restrict__ Al, int rsA,
    const bf16* __restrict__ Bh, const bf16* __restrict__ Bl, int rsB,
    int nChunks, float (&acc)[2][8][4], char* smem, int tid)
{
    uint32_t sb = smem_u32(smem);
    int wid = tid >> 5, lane = tid & 31;
    int mbase = (wid & 3) * 32, nbase = (wid >> 2) * 64;
    int aro = (lane & 7) + ((lane >> 3) & 1) * 8;
    int aco = (lane >> 4) * 8;
    int bro = (lane & 7) + ((lane >> 4) & 1) * 8;
    int bco = ((lane >> 3) & 1) * 8;

    stage_chunk(Ah, Al, rsA, Bh, Bl, rsB, sb, tid);
    CPA_COMMIT();

    for (int ch = 0; ch < nChunks; ch++) {
        int cur = ch & 1;
        if (ch + 1 < nChunks) {
            stage_chunk(Ah + (ch + 1) * 32, Al + (ch + 1) * 32, rsA,
                        Bh + (ch + 1) * 32, Bl + (ch + 1) * 32, rsB,
                        sb + (cur ^ 1) * STAGE, tid);
            CPA_COMMIT();
            CPA_WAIT1();
        } else {
            CPA_WAIT0();
        }
        __syncthreads();
        mma_chunk(sb + cur * STAGE, acc, mbase, nbase, aro, aco, bro, bco);
        __syncthreads();
    }
}

// ---------------- k_tab: index lookup tables ----------------
__global__ void k_tab() {
    int i = blockIdx.x * 256 + threadIdx.x;
    if (i < CC) {
        int qy = i / 38 + 1, qx = i % 38 + 1;
        d_tbase[i] = qy * 40 + qx;
        d_c2pad[i] = CAOFF + qy * 40 + qx;
    }
}

// ---------------- k_prepW: Wt = W^T split hi/lo ----------------
__global__ void k_prepW(const float* __restrict__ W) {
    int i = blockIdx.x * 256 + threadIdx.x;   // 32768
    int dout = i >> 8, k = i & 255;
    float w = W[k * DD + dout];
    bf16 h = __float2bfloat16(w);
    d_Wthi[i] = h;
    d_Wtlo[i] = __float2bfloat16(w - __bfloat162float(h));
}

// ---------------- prep1: bg, bf16 splits, per-pixel |g|^2 ----------------
__global__ __launch_bounds__(128) void k_prep1(const float* __restrict__ g,
                                               const float* __restrict__ mask) {
    int p = blockIdx.x;
    int b = p / HW, r = p - b * HW;
    int d = threadIdx.x;
    size_t gi = (size_t)p * DD + d;
    float gv = g[gi];
    float m = mask[p];
    float bgv = gv * m;
    d_bg[gi] = bgv;
    size_t pi = ((size_t)b * PAD + r) * DD + d;
    bf16 gh = __float2bfloat16(gv);
    bf16 gl = __float2bfloat16(gv - __bfloat162float(gh));
    bf16 bh = __float2bfloat16(bgv);
    bf16 bl = __float2bfloat16(bgv - __bfloat162float(bh));
    d_ghi[pi] = gh; d_glo[pi] = gl;
    d_bghi[pi] = bh; d_bglo[pi] = bl;
    float s = gv * gv;
#pragma unroll
    for (int o = 16; o; o >>= 1) s += __shfl_xor_sync(0xffffffffu, s, o);
    __shared__ float red[4];
    if ((d & 31) == 0) red[d >> 5] = s;
    __syncthreads();
    if (d == 0) d_ng[p] = red[0] + red[1] + red[2] + red[3];
}

// ---------------- prep2 (no smem staging): k1d, wwd directly from L2 ----------------
__global__ __launch_bounds__(256) void k_prep2(const float* __restrict__ mask) {
    int b = blockIdx.y;
    int i = blockIdx.x * 256 + threadIdx.x;   // 0..1791
    const float* ng = d_ng + b * HW;
    const float* ms = mask + b * HW;
    if (i < CC) {
        int r = i / 38, j = i - r * 38;
        float s = 0.f;
#pragma unroll
        for (int dy = 0; dy < 3; dy++)
#pragma unroll
            for (int dx = 0; dx < 3; dx++) {
                int q = (r + dy) * 40 + (j + dx);
                s += ng[q] * ms[q];
            }
        d_k1d[b * CC + i] = s;
    }
    if (i < HW) {
        int y = i / 40, x = i - y * 40;
        float s = 0.f;
#pragma unroll
        for (int oy = -1; oy <= 1; oy++)
#pragma unroll
            for (int ox = -1; ox <= 1; ox++) {
                int yy = y + oy, xx = x + ox;
                if (yy >= 0 && yy < 40 && xx >= 0 && xx < 40) s += ng[yy * 40 + xx];
            }
        d_wwd[b * HW + i] = s;
    }
}

// ---------------- prepT: bgT[d][q] = bg[q][d] (bf16 hi/lo, padded q) ----------------
__global__ __launch_bounds__(256) void k_prepT() {
    int b = blockIdx.y;
    int q0 = blockIdx.x * 64;
    __shared__ bf16 shi[64][DD + 2], slo[64][DD + 2];
    int tid = threadIdx.x;
    for (int i = tid; i < 64 * DD; i += 256) {
        int qq = i >> 7, dc = i & 127;
        int q = q0 + qq;
        bf16 h = __float2bfloat16(0.f), l = h;
        if (q < HW) {
            size_t src = ((size_t)b * PAD + q) * DD + dc;
            h = d_bghi[src]; l = d_bglo[src];
        }
        shi[qq][dc] = h; slo[qq][dc] = l;
    }
    __syncthreads();
    for (int i = tid; i < DD * 64; i += 256) {
        int dr = i >> 6, qq = i & 63;
        size_t dst = ((size_t)b * DD + dr) * PAD + q0 + qq;
        d_bgThi[dst] = shi[qq][dr];
        d_bgTlo[dst] = slo[qq][dr];
    }
}

// ---------------- GEMM1 (mma.sync, cp.async db): M = g @ bg^T ----------------
__global__ __launch_bounds__(256) void k_gemm1_mma() {
    extern __shared__ char smem[];
    int b = blockIdx.z, nt = blockIdx.x, mt = blockIdx.y;
    int tid = threadIdx.x;
    float acc[2][8][4];
#pragma unroll
    for (int i = 0; i < 2; i++)
#pragma unroll
        for (int j = 0; j < 8; j++)
#pragma unroll
            for (int k = 0; k < 4; k++) acc[i][j][k] = 0.f;

    const bf16* Ah = d_ghi + ((size_t)b * PAD + mt * 128) * DD;
    const bf16* Al = d_glo + ((size_t)b * PAD + mt * 128) * DD;
    const bf16* Bh = d_bghi + ((size_t)b * PAD + nt * 128) * DD;
    const bf16* Bl = d_bglo + ((size_t)b * PAD + nt * 128) * DD;
    gemm_core_db(Ah, Al, DD, Bh, Bl, DD, 4, acc, smem, tid);

    int wid = tid >> 5, lane = tid & 31;
    int mw = (wid & 3) * 32, nw = (wid >> 2) * 64;
    float* Mo = d_M + (size_t)b * HW * HW;
#pragma unroll
    for (int mi = 0; mi < 2; mi++)
#pragma unroll
        for (int nj = 0; nj < 8; nj++) {
            int m0 = mt * 128 + mw + mi * 16 + (lane >> 2);
            int n = nt * 128 + nw + nj * 8 + (lane & 3) * 2;
            if (n < HW) {
                if (m0 < HW) *(float2*)&Mo[(size_t)m0 * HW + n] = make_float2(acc[mi][nj][0], acc[mi][nj][1]);
                if (m0 + 8 < HW) *(float2*)&Mo[(size_t)(m0 + 8) * HW + n] = make_float2(acc[mi][nj][2], acc[mi][nj][3]);
            }
        }
}

// ---------------- block reductions, 512 threads ----------------
__device__ __forceinline__ float2 bsum2_512(float a, float b, volatile float* red) {
#pragma unroll
    for (int o = 16; o; o >>= 1) {
        a += __shfl_xor_sync(0xffffffffu, a, o);
        b += __shfl_xor_sync(0xffffffffu, b, o);
    }
    int lane = threadIdx.x & 31;
    int w = threadIdx.x >> 5;
    if (lane == 0) { red[w] = a; red[16 + w] = b; }
    __syncthreads();
    if (threadIdx.x < 32) {
        a = (lane < 16) ? red[lane] : 0.f;
        b = (lane < 16) ? red[16 + lane] : 0.f;
#pragma unroll
        for (int o = 8; o; o >>= 1) {
            a += __shfl_xor_sync(0xffffffffu, a, o);
            b += __shfl_xor_sync(0xffffffffu, b, o);
        }
        if (lane == 0) { red[0] = a; red[16] = b; }
    }
    __syncthreads();
    float2 r = make_float2(red[0], red[16]);
    __syncthreads();
    return r;
}

__device__ __forceinline__ float4 bsum4_512(float a, float b, float c, float d,
                                            volatile float* red) {
#pragma unroll
    for (int o = 16; o; o >>= 1) {
        a += __shfl_xor_sync(0xffffffffu, a, o);
        b += __shfl_xor_sync(0xffffffffu, b, o);
        c += __shfl_xor_sync(0xffffffffu, c, o);
        d += __shfl_xor_sync(0xffffffffu, d, o);
    }
    int lane = threadIdx.x & 31;
    int w = threadIdx.x >> 5;
    if (lane == 0) { red[w] = a; red[16 + w] = b; red[32 + w] = c; red[48 + w] = d; }
    __syncthreads();
    if (threadIdx.x < 32) {
        a = (lane < 16) ? red[lane] : 0.f;
        b = (lane < 16) ? red[16 + lane] : 0.f;
        c = (lane < 16) ? red[32 + lane] : 0.f;
        d = (lane < 16) ? red[48 + lane] : 0.f;
#pragma unroll
        for (int o = 8; o; o >>= 1) {
            a += __shfl_xor_sync(0xffffffffu, a, o);
            b += __shfl_xor_sync(0xffffffffu, b, o);
            c += __shfl_xor_sync(0xffffffffu, c, o);
            d += __shfl_xor_sync(0xffffffffu, d, o);
        }
        if (lane == 0) { red[0] = a; red[16] = b; red[32] = c; red[48] = d; }
    }
    __syncthreads();
    float4 r = make_float4(red[0], red[16], red[32], red[48]);
    __syncthreads();
    return r;
}

// ---------------- k3 (paired locs): softmax for loc0 and loc0+1 per block ----------------
__global__ __launch_bounds__(512) void k3_softmax() {
    int bx = blockIdx.x;            // NB * 800
    int b = bx / 800;
    int pi = bx - b * 800;
    int py = pi / 20, pxp = (pi - py * 20) * 2;
    int loc0 = py * 40 + pxp;
    int tid = threadIdx.x;
    __shared__ float red[64];

    const float* Mb = d_M + (size_t)b * HW * HW;
    float wwd0 = d_wwd[b * HW + loc0];
    float wwd1 = d_wwd[b * HW + loc0 + 1];
    const float* k1 = d_k1d + b * CC;
    bool interior = (py >= 1 && py <= 38 && pxp >= 1 && pxp <= 37);

    float dsr0[3], dsr1[3];
    float s0 = 0.f, s20 = 0.f, s1 = 0.f, s21 = 0.f;
    if (interior) {
        const float* P = Mb + (size_t)loc0 * HW;
#pragma unroll
        for (int e = 0; e < 3; e++) {
            int c = tid + 512 * e;
            int cc = c < CC ? c : CC - 1;
            int base = d_tbase[cc];
            float cs0 = 0.f, cs1 = 0.f;
#pragma unroll
            for (int k = 0; k < 9; k++) {
                cs0 += P[base + OFFL9[k] * (HW + 1)];
                cs1 += P[base + OFFL9[k] * (HW + 1) + HW];
            }
            float dv0 = k1[cc] + wwd0 - 2.f * cs0;
            float dv1 = k1[cc] + wwd1 - 2.f * cs1;
            dsr0[e] = dv0; dsr1[e] = dv1;
            if (c < CC) { s0 += dv0; s20 += dv0 * dv0; s1 += dv1; s21 += dv1 * dv1; }
        }
    } else {
        for (int li = 0; li < 2; li++) {
            int px = pxp + li;
            const float* rowsO[9];
#pragma unroll
            for (int k = 0; k < 9; k++) {
                int y = py + OY9[k], x = px + OX9[k];
                bool v = (y >= 0 && y < 40 && x >= 0 && x < 40);
                rowsO[k] = (v ? (Mb + (size_t)(y * 40 + x) * HW) : d_zrowM) + OFFL9[k];
            }
            float wwd = li ? wwd1 : wwd0;
#pragma unroll
            for (int e = 0; e < 3; e++) {
                int c = tid + 512 * e;
                int cc = c < CC ? c : CC - 1;
                int base = d_tbase[cc];
                float cs = 0.f;
#pragma unroll
                for (int k = 0; k < 9; k++) cs += rowsO[k][base];
                float dv = k1[cc] + wwd - 2.f * cs;
                if (li == 0) dsr0[e] = dv; else dsr1[e] = dv;
                if (c < CC) {
                    if (li == 0) { s0 += dv; s20 += dv * dv; }
                    else { s1 += dv; s21 += dv * dv; }
                }
            }
        }
    }
    float4 mv = bsum4_512(s0, s20, s1, s21, red);
    float mu0 = mv.x * (1.f / CC), ex20 = mv.y * (1.f / CC);
    float mu1 = mv.z * (1.f / CC), ex21 = mv.w * (1.f / CC);
    float inv0 = rsqrtf(fmaxf(ex20 - mu0 * mu0, 0.f));
    float inv1 = rsqrtf(fmaxf(ex21 - mu1 * mu1, 0.f));

    float evr0[3], evr1[3];
    float es0 = 0.f, es1 = 0.f;
#pragma unroll
    for (int e = 0; e < 3; e++) {
        int c = tid + 512 * e;
        {
            float z = (dsr0[e] - mu0) * inv0;
            float a = fabsf(z);
            float ex = __expf(-2.f * a);
            float r = __fdividef(100.f, 1.f + ex);
            float val = (z >= 0.f) ? r : 100.f - r;
            float ev = __expf(-val);
            evr0[e] = ev;
            if (c < CC) es0 += ev;
        }
        {
            float z = (dsr1[e] - mu1) * inv1;
            float a = fabsf(z);
            float ex = __expf(-2.f * a);
            float r = __fdividef(100.f, 1.f + ex);
            float val = (z >= 0.f) ? r : 100.f - r;
            float ev = __expf(-val);
            evr1[e] = ev;
            if (c < CC) es1 += ev;
        }
    }
    float2 est = bsum2_512(es0, es1, red);
    float it0 = 1.f / est.x, it1 = 1.f / est.y;

    float* car0 = d_CApad + (size_t)(b * HW + loc0) * CAS;
    float* car1 = car0 + CAS;
#pragma unroll
    for (int e = 0; e < 3; e++) {
        int c = tid + 512 * e;
        if (c < CC) {
            int idx = d_c2pad[c];
            car0[idx] = evr0[e] * it0;
            car1[idx] = evr1[e] * it1;
        }
    }
}

// ---------------- k4 (paired p's): T rows p0, p0+1 (bf16 hi/lo, padded) ----------------
__global__ __launch_bounds__(256) void k4_buildT() {
    int bx = blockIdx.x;            // NB * 800
    int b = bx / 800;
    int pi = bx - b * 800;
    int py = pi / 20, pxp = (pi - py * 20) * 2;
    int p0 = py * 40 + pxp;
    const float* cab = d_CApad + (size_t)b * HW * CAS;
    bool interior = (py >= 1 && py <= 38 && pxp >= 1 && pxp <= 37);
    size_t tb0 = ((size_t)b * PAD + p0) * PAD;
    size_t tb1 = tb0 + PAD;

    if (interior) {
        const float* Q = cab + (size_t)p0 * CAS + CAOFF;
        for (int q = threadIdx.x; q < HW; q += 256) {
            float t0 = 0.f, t1 = 0.f;
#pragma unroll
            for (int k = 0; k < 9; k++) {
                t0 += Q[q - OFFL9[k] * (CAS + 1)];
                t1 += Q[q - OFFL9[k] * (CAS + 1) + CAS];
            }
            bf16 h0 = __float2bfloat16(t0);
            d_Thi[tb0 + q] = h0;
            d_Tlo[tb0 + q] = __float2bfloat16(t0 - __bfloat162float(h0));
            bf16 h1 = __float2bfloat16(t1);
            d_Thi[tb1 + q] = h1;
            d_Tlo[tb1 + q] = __float2bfloat16(t1 - __bfloat162float(h1));
        }
    } else {
        for (int li = 0; li < 2; li++) {
            int px = pxp + li;
            size_t tb = li ? tb1 : tb0;
            const float* rowsO[9];
#pragma unroll
            for (int k = 0; k < 9; k++) {
                int ly = py - OY9[k], lx = px - OX9[k];
                bool v = (ly >= 0 && ly < 40 && lx >= 0 && lx < 40);
                rowsO[k] = (v ? (cab + (size_t)(ly * 40 + lx) * CAS) : d_zrowCA) + (CAOFF - OFFL9[k]);
            }
            for (int q = threadIdx.x; q < HW; q += 256) {
                float tsum = 0.f;
#pragma unroll
                for (int k = 0; k < 9; k++) tsum += rowsO[k][q];
                bf16 h = __float2bfloat16(tsum);
                d_Thi[tb + q] = h;
                d_Tlo[tb + q] = __float2bfloat16(tsum - __bfloat162float(h));
            }
        }
    }
    if (threadIdx.x < PAD - HW) {
        bf16 z = __float2bfloat16(0.f);
        d_Thi[tb0 + HW + threadIdx.x] = z;
        d_Tlo[tb0 + HW + threadIdx.x] = z;
        d_Thi[tb1 + HW + threadIdx.x] = z;
        d_Tlo[tb1 + HW + threadIdx.x] = z;
    }
}

// ---------------- GEMM2 (mma.sync, cp.async db): Y = T @ bg, 4-way K-split ----------------
// chunks of 32 along K (q): 50 chunks total; split s gets {13,13,12,12}
__global__ __launch_bounds__(256) void k_gemm2_mma() {
    extern __shared__ char smem[];
    int b = blockIdx.z, mt = blockIdx.x, s = blockIdx.y;
    int tid = threadIdx.x;
    int kc0 = (s < 2) ? 13 * s : 26 + 12 * (s - 2);
    int nch = (s < 2) ? 13 : 12;

    float acc[2][8][4];
#pragma unroll
    for (int i = 0; i < 2; i++)
#pragma unroll
        for (int j = 0; j < 8; j++)
#pragma unroll
            for (int k = 0; k < 4; k++) acc[i][j][k] = 0.f;

    const bf16* Ah = d_Thi + ((size_t)b * PAD + mt * 128) * PAD + kc0 * 32;
    const bf16* Al = d_Tlo + ((size_t)b * PAD + mt * 128) * PAD + kc0 * 32;
    const bf16* Bh = d_bgThi + (size_t)b * DD * PAD + kc0 * 32;
    const bf16* Bl = d_bgTlo + (size_t)b * DD * PAD + kc0 * 32;
    gemm_core_db(Ah, Al, PAD, Bh, Bl, PAD, nch, acc, smem, tid);

    int wid = tid >> 5, lane = tid & 31;
    int mw = (wid & 3) * 32, nw = (wid >> 2) * 64;
    float* Yo = d_Y8 + ((size_t)s * NB + b) * HW * DD;
#pragma unroll
    for (int mi = 0; mi < 2; mi++)
#pragma unroll
        for (int nj = 0; nj < 8; nj++) {
            int m0 = mt * 128 + mw + mi * 16 + (lane >> 2);
            int n = nw + nj * 8 + (lane & 3) * 2;
            if (m0 < HW) *(float2*)&Yo[(size_t)m0 * DD + n] = make_float2(acc[mi][nj][0], acc[mi][nj][1]);
            if (m0 + 8 < HW) *(float2*)&Yo[(size_t)(m0 + 8) * DD + n] = make_float2(acc[mi][nj][2], acc[mi][nj][3]);
        }
}

// ---------------- k5 (mma): out = ELU(con @ W + bias), con built on the fly ----------------
__global__ __launch_bounds__(256) void k5_mma(const float* __restrict__ mask,
                                              const float* __restrict__ bias,
                                              float* __restrict__ out) {
    __shared__ bf16 smem5[4 * BUFE];   // 40 KB: Ah, Al, Bh, Bl
    int mt = blockIdx.x, b = blockIdx.y;
    int tid = threadIdx.x;
    int P0 = mt * 128;
    uint32_t sb = smem_u32(smem5);
    const size_t YSTR = (size_t)NB * HW * DD;

    int wid = tid >> 5, lane = tid & 31;
    int mbase = (wid & 3) * 32, nbase = (wid >> 2) * 64;
    int aro = (lane & 7) + ((lane >> 3) & 1) * 8;
    int aco = (lane >> 4) * 8;
    int bro = (lane & 7) + ((lane >> 4) & 1) * 8;
    int bco = ((lane >> 3) & 1) * 8;

    int ar = tid >> 1, ac0 = (tid & 1) * 16;
    int pa = P0 + ar;
    int pc = pa < HW ? pa : HW - 1;
    float mval = mask[b * HW + pc];
    float w1m = (1.f - mval) * (1.f / 9.f);
    size_t gbase = ((size_t)b * HW + pc) * DD;

    float acc[2][8][4];
#pragma unroll
    for (int i = 0; i < 2; i++)
#pragma unroll
        for (int j = 0; j < 8; j++)
#pragma unroll
            for (int k = 0; k < 4; k++) acc[i][j][k] = 0.f;

    for (int ch = 0; ch < 8; ch++) {
        int k0 = ch * 32;
        __syncthreads();
#pragma unroll
        for (int i = tid; i < 512; i += 256) {
            int r = i >> 2, c = (i & 3) * 8;
            uint32_t so = (uint32_t)((r * SSTR + c) * 2);
            CPA16(sb + 2 * BUFB + so, d_Wthi + r * 256 + k0 + c);
            CPA16(sb + 3 * BUFB + so, d_Wtlo + r * 256 + k0 + c);
        }
        if (ch < 4) {
#pragma unroll
            for (int i = tid; i < 512; i += 256) {
                int r = i >> 2, c = (i & 3) * 8;
                uint32_t so = (uint32_t)((r * SSTR + c) * 2);
                CPA16(sb + so,        d_ghi + ((size_t)b * PAD + P0 + r) * DD + k0 + c);
                CPA16(sb + BUFB + so, d_glo + ((size_t)b * PAD + P0 + r) * DD + k0 + c);
            }
        } else {
            int d0 = (k0 - 128) + ac0;
            size_t gi = gbase + d0;
            float v[16];
#pragma unroll
            for (int j = 0; j < 16; j += 4) {
                float4 bgv = *(const float4*)&d_bg[gi + j];
                float4 y0 = *(const float4*)&d_Y8[0 * YSTR + gi + j];
                float4 y1 = *(const float4*)&d_Y8[1 * YSTR + gi + j];
                float4 y2 = *(const float4*)&d_Y8[2 * YSTR + gi + j];
                float4 y3 = *(const float4*)&d_Y8[3 * YSTR + gi + j];
                v[j + 0] = bgv.x + (y0.x + y1.x + y2.x + y3.x) * w1m;
                v[j + 1] = bgv.y + (y0.y + y1.y + y2.y + y3.y) * w1m;
                v[j + 2] = bgv.z + (y0.z + y1.z + y2.z + y3.z) * w1m;
                v[j + 3] = bgv.w + (y0.w + y1.w + y2.w + y3.w) * w1m;
            }
            HU8 hh, ll;
#pragma unroll
            for (int g2 = 0; g2 < 2; g2++) {
#pragma unroll
                for (int j = 0; j < 8; j++) {
                    float fv = v[g2 * 8 + j];
                    bf16 h = __float2bfloat16(fv);
                    hh.h[j] = h;
                    ll.h[j] = __float2bfloat16(fv - __bfloat162float(h));
                }
                *(uint4*)((char*)smem5 + (ar * SSTR + ac0 + g2 * 8) * 2) = hh.u;
                *(uint4*)((char*)smem5 + BUFB + (ar * SSTR + ac0 + g2 * 8) * 2) = ll.u;
            }
        }
        CPA_COMMIT();
        CPA_WAIT0();
        __syncthreads();
        mma_chunk(sb, acc, mbase, nbase, aro, aco, bro, bco);
    }

    int mw = (wid & 3) * 32, nw = (wid >> 2) * 64;
#pragma unroll
    for (int mi = 0; mi < 2; mi++)
#pragma unroll
        for (int nj = 0; nj < 8; nj++) {
            int m0 = P0 + mw + mi * 16 + (lane >> 2);
            int n = nw + nj * 8 + (lane & 3) * 2;
            float b0 = bias[n], b1 = bias[n + 1];
            float v0 = acc[mi][nj][0] + b0, v1 = acc[mi][nj][1] + b1;
            float v2 = acc[mi][nj][2] + b0, v3 = acc[mi][nj][3] + b1;
            v0 = v0 > 0.f ? v0 : expm1f(v0);
            v1 = v1 > 0.f ? v1 : expm1f(v1);
            v2 = v2 > 0.f ? v2 : expm1f(v2);
            v3 = v3 > 0.f ? v3 : expm1f(v3);
            if (m0 < HW) *(float2*)&out[((size_t)b * HW + m0) * DD + n] = make_float2(v0, v1);
            if (m0 + 8 < HW) *(float2*)&out[((size_t)b * HW + m0 + 8) * DD + n] = make_float2(v2, v3);
        }
}

// ---------------- launch ----------------
extern "C" void kernel_launch(void* const* d_in, const int* in_sizes, int n_in,
                              void* d_out, int out_size) {
    const float* g    = (const float*)d_in[0];
    const float* mask = (const float*)d_in[1];
    const float* Wm   = (const float*)d_in[2];
    const float* bias = (const float*)d_in[3];
    float* out = (float*)d_out;

    cudaFuncSetAttribute(k_gemm1_mma, cudaFuncAttributeMaxDynamicSharedMemorySize, GSMEM);
    cudaFuncSetAttribute(k_gemm2_mma, cudaFuncAttributeMaxDynamicSharedMemorySize, GSMEM);

    k_tab<<<6, 256>>>();
    k_prepW<<<128, 256>>>(Wm);
    k_prep1<<<NB * HW, 128>>>(g, mask);
    k_prep2<<<dim3(7, NB), 256>>>(mask);
    k_prepT<<<dim3(PAD / 64, NB), 256>>>();
    k_gemm1_mma<<<dim3(MT, MT, NB), 256, GSMEM>>>();
    k3_softmax<<<NB * 800, 512>>>();
    k4_buildT<<<NB * 800, 256>>>();
    k_gemm2_mma<<<dim3(MT, NSPLIT, NB), 256, GSMEM>>>();
    k5_mma<<<dim3(MT, NB), 256>>>(mask, bias, out);
}